// round 11
// baseline (speedup 1.0000x reference)
#include <cuda_runtime.h>
#include <cuda_bf16.h>
#include <cuda_fp16.h>
#include <cstdint>
#include <math.h>

// ---------------------------------------------------------------------------
// Problem constants
// ---------------------------------------------------------------------------
#define LNUM 2
#define DMODEL 256
#define DFF 1024
#define NH 8
#define NP 4
#define CIN 512
#define BATCH 8
#define HH 64
#define WW 64
#define HW (HH * WW)            // 4096
#define MROWS (BATCH * HW)      // 32768
#define EPSV 1e-5f
#define NOAP 128                // padded offsets(64)+attn(32)+pad(32) width
#define RS 40                   // smem row stride in halves (conflict-free)

// ---------------------------------------------------------------------------
// Scratch (device globals; no dynamic allocation allowed)
// ---------------------------------------------------------------------------
__device__ float g_XT[(size_t)MROWS * CIN];
__device__ float g_SRC[(size_t)MROWS * DMODEL];
__device__ float g_Q[(size_t)MROWS * DMODEL];
__device__ float g_VAL[(size_t)MROWS * DMODEL];
__device__ float g_T1[(size_t)MROWS * DMODEL];
__device__ float g_OA[(size_t)MROWS * NOAP];
__device__ float g_H[(size_t)MROWS * DFF];
__device__ float g_WvalT[LNUM][DMODEL * DMODEL];
__device__ float g_WoT[LNUM][DMODEL * DMODEL];
__device__ float g_W1T[LNUM][DMODEL * DFF];
__device__ float g_W2T[LNUM][DFF * DMODEL];
__device__ float g_WOAT[NOAP * DMODEL];
__device__ float g_bOA[NOAP];
__device__ float g_alpha1[DMODEL], g_beta1[DMODEL];
__device__ float g_alpha2[CIN],    g_beta2[CIN];

// ---------------------------------------------------------------------------
// FP16 tensor-core GEMM (mma.sync m16n8k16):
//   C[M,N] = act((A[M,K] @ BT[N,K]^T) * alpha[n] + beta[n])
// A row-major [M][K] fp32; BT row-major [N][K] fp32 (weight pre-transposed).
// Block tile 128x128, BK=32, 8 warps (warp tile 64x32), double-buffered smem.
// M % 128 == 0, N % 128 == 0, K % 32 == 0.
// ---------------------------------------------------------------------------
__global__ void __launch_bounds__(256)
gemm_f16_kernel(const float* __restrict__ A, const float* __restrict__ BT,
                float* __restrict__ C, int M, int N, int K,
                const float* __restrict__ alpha, const float* __restrict__ beta,
                int do_relu)
{
    __shared__ __half As[2][128 * RS];
    __shared__ __half Bs[2][128 * RS];

    const int t    = threadIdx.x;
    const int bm   = blockIdx.y * 128;
    const int bn   = blockIdx.x * 128;
    const int warp = t >> 5;
    const int lane = t & 31;
    const int wm   = (warp & 1) * 64;
    const int wn   = (warp >> 1) * 32;
    const int gid  = lane >> 2;
    const int q    = lane & 3;

    // global staging: thread handles one (row, 16-k half) of A and of B
    const int g_row = t >> 1;         // 0..127
    const int g_kh  = (t & 1) * 16;   // 0 or 16

    float4 ar[4], br[4];

    float acc[4][4][4];
    #pragma unroll
    for (int mi = 0; mi < 4; mi++)
        #pragma unroll
        for (int ni = 0; ni < 4; ni++)
            #pragma unroll
            for (int r = 0; r < 4; r++) acc[mi][ni][r] = 0.0f;

    const int nk = K >> 5;

    // store 16 staged floats as 16 halves (two uint4) into smem row
    auto stage_store = [&](int buf) {
        __half2 ha[8], hb[8];
        #pragma unroll
        for (int i = 0; i < 4; i++) {
            ha[2 * i + 0] = __floats2half2_rn(ar[i].x, ar[i].y);
            ha[2 * i + 1] = __floats2half2_rn(ar[i].z, ar[i].w);
            hb[2 * i + 0] = __floats2half2_rn(br[i].x, br[i].y);
            hb[2 * i + 1] = __floats2half2_rn(br[i].z, br[i].w);
        }
        __half* pa = &As[buf][g_row * RS + g_kh];
        __half* pb = &Bs[buf][g_row * RS + g_kh];
        *(uint4*)pa       = *(uint4*)&ha[0];
        *(uint4*)(pa + 8) = *(uint4*)&ha[4];
        *(uint4*)pb       = *(uint4*)&hb[0];
        *(uint4*)(pb + 8) = *(uint4*)&hb[4];
    };

    // prologue: chunk 0 -> buf 0
    #pragma unroll
    for (int i = 0; i < 4; i++) {
        ar[i] = *(const float4*)(A  + (size_t)(bm + g_row) * K + g_kh + i * 4);
        br[i] = *(const float4*)(BT + (size_t)(bn + g_row) * K + g_kh + i * 4);
    }
    stage_store(0);
    __syncthreads();

    for (int kc = 0; kc < nk; kc++) {
        const int cur = kc & 1;
        const int nxt = cur ^ 1;
        if (kc + 1 < nk) {
            int k0 = (kc + 1) << 5;
            #pragma unroll
            for (int i = 0; i < 4; i++) {
                ar[i] = *(const float4*)(A  + (size_t)(bm + g_row) * K + k0 + g_kh + i * 4);
                br[i] = *(const float4*)(BT + (size_t)(bn + g_row) * K + k0 + g_kh + i * 4);
            }
        }

        #pragma unroll
        for (int ks = 0; ks < 2; ks++) {
            const int kb = ks * 16;
            uint32_t af[4][4], bf[4][2];
            #pragma unroll
            for (int mi = 0; mi < 4; mi++) {
                const __half* r0 = &As[cur][(wm + mi * 16 + gid) * RS + kb + 2 * q];
                const __half* r1 = r0 + 8 * RS;
                af[mi][0] = *(const uint32_t*)r0;
                af[mi][1] = *(const uint32_t*)r1;
                af[mi][2] = *(const uint32_t*)(r0 + 8);
                af[mi][3] = *(const uint32_t*)(r1 + 8);
            }
            #pragma unroll
            for (int ni = 0; ni < 4; ni++) {
                const __half* n0 = &Bs[cur][(wn + ni * 8 + gid) * RS + kb + 2 * q];
                bf[ni][0] = *(const uint32_t*)n0;
                bf[ni][1] = *(const uint32_t*)(n0 + 8);
            }
            #pragma unroll
            for (int mi = 0; mi < 4; mi++)
                #pragma unroll
                for (int ni = 0; ni < 4; ni++) {
                    asm volatile(
                        "mma.sync.aligned.m16n8k16.row.col.f32.f16.f16.f32 "
                        "{%0,%1,%2,%3}, {%4,%5,%6,%7}, {%8,%9}, {%0,%1,%2,%3};\n"
                        : "+f"(acc[mi][ni][0]), "+f"(acc[mi][ni][1]),
                          "+f"(acc[mi][ni][2]), "+f"(acc[mi][ni][3])
                        : "r"(af[mi][0]), "r"(af[mi][1]), "r"(af[mi][2]), "r"(af[mi][3]),
                          "r"(bf[ni][0]), "r"(bf[ni][1]));
                }
        }

        if (kc + 1 < nk) {
            stage_store(nxt);
            __syncthreads();
        }
    }

    // epilogue (N multiple of 128 -> no masking)
    #pragma unroll
    for (int mi = 0; mi < 4; mi++) {
        #pragma unroll
        for (int ni = 0; ni < 4; ni++) {
            int col = bn + wn + ni * 8 + 2 * q;
            float al0 = alpha ? alpha[col]     : 1.0f;
            float al1 = alpha ? alpha[col + 1] : 1.0f;
            float be0 = beta  ? beta[col]      : 0.0f;
            float be1 = beta  ? beta[col + 1]  : 0.0f;
            #pragma unroll
            for (int h = 0; h < 2; h++) {
                int row = bm + wm + mi * 16 + gid + h * 8;
                float v0 = acc[mi][ni][2 * h + 0] * al0 + be0;
                float v1 = acc[mi][ni][2 * h + 1] * al1 + be1;
                if (do_relu) { v0 = fmaxf(v0, 0.f); v1 = fmaxf(v1, 0.f); }
                *(float2*)(C + (size_t)row * N + col) = make_float2(v0, v1);
            }
        }
    }
}

// ---------------------------------------------------------------------------
// Transposes
// ---------------------------------------------------------------------------
__global__ void transpose_kernel(const float* __restrict__ in, float* __restrict__ out,
                                 int R, int C)
{
    __shared__ float tile[32][33];
    size_t boff = (size_t)blockIdx.z * R * C;
    in += boff; out += boff;
    int c0 = blockIdx.x * 32;
    int r0 = blockIdx.y * 32;
    int x = threadIdx.x, y = threadIdx.y;
    #pragma unroll
    for (int j = 0; j < 32; j += 8)
        tile[y + j][x] = in[(size_t)(r0 + y + j) * C + c0 + x];
    __syncthreads();
    #pragma unroll
    for (int j = 0; j < 32; j += 8)
        out[(size_t)(c0 + y + j) * R + r0 + x] = tile[x][y + j];
}

__global__ void transpose_bn_relu_kernel(const float* __restrict__ in, float* __restrict__ out,
                                         const float* __restrict__ alpha,
                                         const float* __restrict__ beta,
                                         int R, int C)
{
    __shared__ float tile[32][33];
    size_t boff = (size_t)blockIdx.z * R * C;
    in += boff; out += boff;
    int c0 = blockIdx.x * 32;
    int r0 = blockIdx.y * 32;
    int x = threadIdx.x, y = threadIdx.y;
    #pragma unroll
    for (int j = 0; j < 32; j += 8)
        tile[y + j][x] = in[(size_t)(r0 + y + j) * C + c0 + x];
    __syncthreads();
    #pragma unroll
    for (int j = 0; j < 32; j += 8) {
        int ch = c0 + y + j;
        float v = tile[x][y + j] * alpha[ch] + beta[ch];
        out[(size_t)ch * R + r0 + x] = fmaxf(v, 0.0f);
    }
}

__global__ void prep_bn_kernel(const float* g1, const float* b1, const float* m1, const float* v1,
                               const float* g2, const float* b2, const float* m2, const float* v2)
{
    int i = threadIdx.x + blockIdx.x * blockDim.x;
    if (i < DMODEL) {
        float a = g1[i] * rsqrtf(v1[i] + EPSV);
        g_alpha1[i] = a;
        g_beta1[i]  = b1[i] - m1[i] * a;
    }
    if (i < CIN) {
        float a = g2[i] * rsqrtf(v2[i] + EPSV);
        g_alpha2[i] = a;
        g_beta2[i]  = b2[i] - m2[i] * a;
    }
}

__global__ void bcast_q_kernel(const float* __restrict__ qe, float* __restrict__ Q)
{
    size_t i = (size_t)blockIdx.x * blockDim.x + threadIdx.x;
    size_t per = (size_t)HW * DMODEL;
    if (i < per) {
        float v = qe[i];
        #pragma unroll
        for (int b = 0; b < BATCH; b++)
            Q[(size_t)b * per + i] = v;
    }
}

// Build WOAT[n][k] (transposed, padded to NOAP=128 rows) + padded bias
__global__ void concat_woa_kernel(const float* __restrict__ Woff_i, const float* __restrict__ boff_i,
                                  const float* __restrict__ Wattn_i, const float* __restrict__ battn_i)
{
    int i = blockIdx.x * blockDim.x + threadIdx.x;
    if (i < NOAP * DMODEL) {
        int n = i >> 8;
        int k = i & 255;
        float v = 0.0f;
        if (n < 64)      v = Woff_i[k * 64 + n];
        else if (n < 96) v = Wattn_i[k * 32 + (n - 64)];
        g_WOAT[i] = v;
    }
    if (i < NOAP)
        g_bOA[i] = (i < 64) ? boff_i[i] : (i < 96 ? battn_i[i - 64] : 0.0f);
}

// ---------------------------------------------------------------------------
// Deformable sampling with fused per-head softmax.
// OA row (stride NOAP=128): [offsets: 64][attn logits: 32][pad: 32]
// ---------------------------------------------------------------------------
__device__ __forceinline__ float fetch_val(const float* __restrict__ vb, int xi, int yi, int c)
{
    if (xi < 0 || xi >= WW || yi < 0 || yi >= HH) return 0.0f;
    return vb[((size_t)(yi * WW + xi)) * DMODEL + c];
}

__global__ void __launch_bounds__(256)
deform_sample_kernel(const float* __restrict__ VAL, const float* __restrict__ OA,
                     float* __restrict__ O)
{
    int m = blockIdx.x;
    int b = m >> 12;
    int pix = m & (HW - 1);
    int t = threadIdx.x;
    int head = t >> 5;
    int c = t;

    float rx = ((pix & (WW - 1)) + 0.5f) * (1.0f / WW);
    float ry = ((pix >> 6) + 0.5f) * (1.0f / HH);

    const float* vb   = VAL + (size_t)b * HW * DMODEL;
    const float* offm = OA + (size_t)m * NOAP + head * (NP * 2);
    const float* lg   = OA + (size_t)m * NOAP + 64 + head * NP;

    float l0 = lg[0], l1 = lg[1], l2 = lg[2], l3 = lg[3];
    float mx = fmaxf(fmaxf(l0, l1), fmaxf(l2, l3));
    float e0 = __expf(l0 - mx), e1 = __expf(l1 - mx);
    float e2 = __expf(l2 - mx), e3 = __expf(l3 - mx);
    float inv = 1.0f / (e0 + e1 + e2 + e3);
    float w[4] = { e0 * inv, e1 * inv, e2 * inv, e3 * inv };

    float acc = 0.0f;
    #pragma unroll
    for (int p = 0; p < NP; p++) {
        float lx = rx + offm[p * 2 + 0] * (1.0f / WW);
        float ly = ry + offm[p * 2 + 1] * (1.0f / HH);
        float gx = lx * WW - 0.5f;
        float gy = ly * HH - 0.5f;
        float fx = floorf(gx), fy = floorf(gy);
        int x0 = (int)fx, y0 = (int)fy;
        float wx = gx - fx, wy = gy - fy;
        float v00 = fetch_val(vb, x0,     y0,     c);
        float v10 = fetch_val(vb, x0 + 1, y0,     c);
        float v01 = fetch_val(vb, x0,     y0 + 1, c);
        float v11 = fetch_val(vb, x0 + 1, y0 + 1, c);
        float s = v00 * (1.f - wx) * (1.f - wy) + v10 * wx * (1.f - wy)
                + v01 * (1.f - wx) * wy         + v11 * wx * wy;
        acc = fmaf(w[p], s, acc);
    }
    O[(size_t)m * DMODEL + c] = acc;
}

// ---------------------------------------------------------------------------
// Residual + LayerNorm (in place on Q)
// ---------------------------------------------------------------------------
__global__ void __launch_bounds__(256)
resid_ln_kernel(float* __restrict__ Q, const float* __restrict__ T,
                const float* __restrict__ gamma, const float* __restrict__ beta)
{
    int row  = blockIdx.x * 8 + (threadIdx.x >> 5);
    int lane = threadIdx.x & 31;
    const float4* qr = (const float4*)(Q + (size_t)row * DMODEL);
    const float4* tr = (const float4*)(T + (size_t)row * DMODEL);

    float x[8];
    float sum = 0.f, sumsq = 0.f;
    #pragma unroll
    for (int i = 0; i < 2; i++) {
        float4 a = qr[lane + i * 32];
        float4 b = tr[lane + i * 32];
        float v0 = a.x + b.x, v1 = a.y + b.y, v2 = a.z + b.z, v3 = a.w + b.w;
        x[i * 4 + 0] = v0; x[i * 4 + 1] = v1; x[i * 4 + 2] = v2; x[i * 4 + 3] = v3;
        sum += v0 + v1 + v2 + v3;
        sumsq += v0 * v0 + v1 * v1 + v2 * v2 + v3 * v3;
    }
    #pragma unroll
    for (int s = 16; s > 0; s >>= 1) {
        sum   += __shfl_xor_sync(0xffffffffu, sum, s);
        sumsq += __shfl_xor_sync(0xffffffffu, sumsq, s);
    }
    float mean = sum * (1.0f / DMODEL);
    float var  = sumsq * (1.0f / DMODEL) - mean * mean;
    float rstd = rsqrtf(var + EPSV);

    float4* qw = (float4*)(Q + (size_t)row * DMODEL);
    #pragma unroll
    for (int i = 0; i < 2; i++) {
        int e = (lane + i * 32) * 4;
        float4 o;
        o.x = (x[i * 4 + 0] - mean) * rstd * gamma[e + 0] + beta[e + 0];
        o.y = (x[i * 4 + 1] - mean) * rstd * gamma[e + 1] + beta[e + 1];
        o.z = (x[i * 4 + 2] - mean) * rstd * gamma[e + 2] + beta[e + 2];
        o.w = (x[i * 4 + 3] - mean) * rstd * gamma[e + 3] + beta[e + 3];
        qw[lane + i * 32] = o;
    }
}

// ---------------------------------------------------------------------------
// Launch
// ---------------------------------------------------------------------------
extern "C" void kernel_launch(void* const* d_in, const int* in_sizes, int n_in,
                              void* d_out, int out_size)
{
    const float* x      = (const float*)d_in[0];
    const float* W_in   = (const float*)d_in[1];
    const float* bn1_g  = (const float*)d_in[2];
    const float* bn1_b  = (const float*)d_in[3];
    const float* bn1_m  = (const float*)d_in[4];
    const float* bn1_v  = (const float*)d_in[5];
    const float* qembed = (const float*)d_in[6];
    const float* Woff   = (const float*)d_in[7];
    const float* boff   = (const float*)d_in[8];
    const float* Wattn  = (const float*)d_in[9];
    const float* battn  = (const float*)d_in[10];
    const float* Wval   = (const float*)d_in[11];
    const float* bval   = (const float*)d_in[12];
    const float* Wo     = (const float*)d_in[13];
    const float* bo     = (const float*)d_in[14];
    const float* ln1_g  = (const float*)d_in[15];
    const float* ln1_b  = (const float*)d_in[16];
    const float* W1     = (const float*)d_in[17];
    const float* b1     = (const float*)d_in[18];
    const float* W2     = (const float*)d_in[19];
    const float* b2     = (const float*)d_in[20];
    const float* ln2_g  = (const float*)d_in[21];
    const float* ln2_b  = (const float*)d_in[22];
    const float* W_out  = (const float*)d_in[23];
    const float* bn2_g  = (const float*)d_in[24];
    const float* bn2_b  = (const float*)d_in[25];
    const float* bn2_m  = (const float*)d_in[26];
    const float* bn2_v  = (const float*)d_in[27];
    float* out = (float*)d_out;

    float *XT, *SRC, *Q, *VAL, *T1, *OA, *H, *WvalT, *WoT, *W1T, *W2T, *WOAT, *bOA;
    float *al1, *be1, *al2, *be2;
    cudaGetSymbolAddress((void**)&XT,    g_XT);
    cudaGetSymbolAddress((void**)&SRC,   g_SRC);
    cudaGetSymbolAddress((void**)&Q,     g_Q);
    cudaGetSymbolAddress((void**)&VAL,   g_VAL);
    cudaGetSymbolAddress((void**)&T1,    g_T1);
    cudaGetSymbolAddress((void**)&OA,    g_OA);
    cudaGetSymbolAddress((void**)&H,     g_H);
    cudaGetSymbolAddress((void**)&WvalT, g_WvalT);
    cudaGetSymbolAddress((void**)&WoT,   g_WoT);
    cudaGetSymbolAddress((void**)&W1T,   g_W1T);
    cudaGetSymbolAddress((void**)&W2T,   g_W2T);
    cudaGetSymbolAddress((void**)&WOAT,  g_WOAT);
    cudaGetSymbolAddress((void**)&bOA,   g_bOA);
    cudaGetSymbolAddress((void**)&al1,   g_alpha1);
    cudaGetSymbolAddress((void**)&be1,   g_beta1);
    cudaGetSymbolAddress((void**)&al2,   g_alpha2);
    cudaGetSymbolAddress((void**)&be2,   g_beta2);

    dim3 tb32(32, 8);

    // launches 0..4 (so launch #5 — ncu capture target — is the proj_in GEMM)
    transpose_kernel<<<dim3(HW / 32, CIN / 32, BATCH), tb32>>>(x, XT, CIN, HW);
    prep_bn_kernel<<<1, 512>>>(bn1_g, bn1_b, bn1_m, bn1_v, bn2_g, bn2_b, bn2_m, bn2_v);
    transpose_kernel<<<dim3(DMODEL / 32, DMODEL / 32, 1), tb32>>>(Wval, WvalT, DMODEL, DMODEL);
    transpose_kernel<<<dim3(DMODEL / 32, DMODEL / 32, 1), tb32>>>(Wo, WoT, DMODEL, DMODEL);
    transpose_kernel<<<dim3(DFF / 32, DMODEL / 32, 1), tb32>>>(W1, W1T, DMODEL, DFF);

    // launch 5: proj_in GEMM. B = W_in (D,CIN) is already [N][K] K-major.
    gemm_f16_kernel<<<dim3(DMODEL / 128, MROWS / 128), 256>>>(XT, W_in, SRC,
                                                              MROWS, DMODEL, CIN,
                                                              al1, be1, 1);

    // remaining weight transposes
    transpose_kernel<<<dim3(DMODEL / 32, DFF / 32, 1), tb32>>>(W2, W2T, DFF, DMODEL);
    transpose_kernel<<<dim3(DMODEL / 32, DMODEL / 32, 1), tb32>>>(
        Wval + (size_t)DMODEL * DMODEL, WvalT + (size_t)DMODEL * DMODEL, DMODEL, DMODEL);
    transpose_kernel<<<dim3(DMODEL / 32, DMODEL / 32, 1), tb32>>>(
        Wo + (size_t)DMODEL * DMODEL, WoT + (size_t)DMODEL * DMODEL, DMODEL, DMODEL);
    transpose_kernel<<<dim3(DFF / 32, DMODEL / 32, 1), tb32>>>(
        W1 + (size_t)DMODEL * DFF, W1T + (size_t)DMODEL * DFF, DMODEL, DFF);
    transpose_kernel<<<dim3(DMODEL / 32, DFF / 32, 1), tb32>>>(
        W2 + (size_t)DFF * DMODEL, W2T + (size_t)DFF * DMODEL, DFF, DMODEL);

    {
        int per = HW * DMODEL;
        bcast_q_kernel<<<(per + 255) / 256, 256>>>(qembed, Q);
    }

    for (int i = 0; i < LNUM; i++) {
        const float* WvalT_i = WvalT + (size_t)i * DMODEL * DMODEL;
        const float* bval_i  = bval  + (size_t)i * DMODEL;
        const float* Woff_i  = Woff  + (size_t)i * DMODEL * (NH * NP * 2);
        const float* boff_i  = boff  + (size_t)i * (NH * NP * 2);
        const float* Wattn_i = Wattn + (size_t)i * DMODEL * (NH * NP);
        const float* battn_i = battn + (size_t)i * (NH * NP);
        const float* WoT_i   = WoT   + (size_t)i * DMODEL * DMODEL;
        const float* bo_i    = bo    + (size_t)i * DMODEL;
        const float* W1T_i   = W1T   + (size_t)i * DMODEL * DFF;
        const float* b1_i    = b1    + (size_t)i * DFF;
        const float* W2T_i   = W2T   + (size_t)i * DFF * DMODEL;
        const float* b2_i    = b2    + (size_t)i * DMODEL;

        concat_woa_kernel<<<(NOAP * DMODEL + 255) / 256, 256>>>(Woff_i, boff_i,
                                                                Wattn_i, battn_i);

        gemm_f16_kernel<<<dim3(DMODEL / 128, MROWS / 128), 256>>>(SRC, WvalT_i, VAL,
                                                                  MROWS, DMODEL, DMODEL,
                                                                  nullptr, bval_i, 0);
        gemm_f16_kernel<<<dim3(NOAP / 128, MROWS / 128), 256>>>(Q, WOAT, OA,
                                                                MROWS, NOAP, DMODEL,
                                                                nullptr, bOA, 0);

        deform_sample_kernel<<<MROWS, 256>>>(VAL, OA, H);

        gemm_f16_kernel<<<dim3(DMODEL / 128, MROWS / 128), 256>>>(H, WoT_i, T1,
                                                                  MROWS, DMODEL, DMODEL,
                                                                  nullptr, bo_i, 0);
        resid_ln_kernel<<<MROWS / 8, 256>>>(Q, T1, ln1_g + (size_t)i * DMODEL,
                                            ln1_b + (size_t)i * DMODEL);
        gemm_f16_kernel<<<dim3(DFF / 128, MROWS / 128), 256>>>(Q, W1T_i, H,
                                                               MROWS, DFF, DMODEL,
                                                               nullptr, b1_i, 1);
        gemm_f16_kernel<<<dim3(DMODEL / 128, MROWS / 128), 256>>>(H, W2T_i, T1,
                                                                  MROWS, DMODEL, DFF,
                                                                  nullptr, b2_i, 0);
        resid_ln_kernel<<<MROWS / 8, 256>>>(Q, T1, ln2_g + (size_t)i * DMODEL,
                                            ln2_b + (size_t)i * DMODEL);
    }

    // proj_out: B = W_out (CIN,D) already [N][K] K-major.
    gemm_f16_kernel<<<dim3(CIN / 128, MROWS / 128), 256>>>(Q, W_out, H,
                                                           MROWS, CIN, DMODEL,
                                                           nullptr, nullptr, 0);
    transpose_bn_relu_kernel<<<dim3(CIN / 32, HW / 32, BATCH), tb32>>>(H, out, al2, be2,
                                                                       HW, CIN);
}

// round 12
// speedup vs baseline: 1.1284x; 1.1284x over previous
#include <cuda_runtime.h>
#include <cuda_bf16.h>
#include <cstdint>
#include <math.h>

// ---------------------------------------------------------------------------
// Problem constants
// ---------------------------------------------------------------------------
#define LNUM 2
#define DMODEL 256
#define DFF 1024
#define NH 8
#define NP 4
#define CIN 512
#define BATCH 8
#define HH 64
#define WW 64
#define HW (HH * WW)            // 4096
#define MROWS (BATCH * HW)      // 32768
#define EPSV 1e-5f
#define NOA 96                  // merged offsets(64)+attn(32)

// ---------------------------------------------------------------------------
// Scratch (device globals; no dynamic allocation allowed)
// ---------------------------------------------------------------------------
__device__ float g_SRC[(size_t)MROWS * DMODEL];
__device__ float g_Q[(size_t)MROWS * DMODEL];
__device__ float g_VAL[(size_t)MROWS * DMODEL];
__device__ float g_T1[(size_t)MROWS * DMODEL];
__device__ float g_OA[(size_t)MROWS * NOA];
__device__ float g_H[(size_t)MROWS * DFF];
__device__ float g_WIT[CIN * DMODEL];    // W_in^T  [CIN][D]
__device__ float g_WOT[DMODEL * CIN];    // W_out^T [D][CIN]
__device__ float g_WOA[DMODEL * NOA];    // [k][n]
__device__ float g_bOA[NOA];
__device__ float g_alpha1[DMODEL], g_beta1[DMODEL];
__device__ float g_alpha2[CIN],    g_beta2[CIN];

// ---------------------------------------------------------------------------
// tf32 conversion (round-to-nearest)
// ---------------------------------------------------------------------------
__device__ __forceinline__ unsigned f2tf(float f)
{
    unsigned r;
    asm("cvt.rna.tf32.f32 %0, %1;" : "=r"(r) : "f"(f));
    return r;
}

// ---------------------------------------------------------------------------
// TF32 tensor-core GEMM, double-buffered smem (R6-proven core).
//   C[M,N] = act((A[M,K] @ B[K,N]) * alpha[n] + beta[n])
// Block tile 128x128, BK=16, 8 warps (warp tile 64x32), mma.m16n8k8.
// ACOL=1:  A is x-layout [b][k][hw] (K-major per batch, row stride HW);
//          M-tile must lie within one batch (128 | HW). Staged as [k][m].
// OTRANS=1: C is out-layout [b][c][hw]; epilogue restages via smem and
//          writes coalesced channel rows with BN(alpha,beta)+ReLU fused.
// M % 128 == 0, K % 16 == 0, N % 2 == 0 (cols >= N masked out, grid-x full
// tiles assumed for OTRANS / ACOL paths).
// ---------------------------------------------------------------------------
template<int ACOL, int OTRANS>
__global__ void __launch_bounds__(256)
gemm_tf32_kernel(const float* __restrict__ A, const float* __restrict__ B,
                 float* __restrict__ C, int M, int N, int K,
                 const float* __restrict__ alpha, const float* __restrict__ beta,
                 int do_relu)
{
    // raw smem, aliased three ways
    __shared__ __align__(16) unsigned sraw[2 * 128 * 20 + 2 * 16 * 136];
    unsigned (*As)[128][20]  = (unsigned(*)[128][20])sraw;              // AROW
    unsigned (*Ask)[16][136] = (unsigned(*)[16][136])sraw;              // ACOL
    unsigned (*Bs)[16][136]  = (unsigned(*)[16][136])(sraw + 2 * 128 * 20);
    float    (*cbuf)[132]    = (float(*)[132])sraw;                     // OTRANS epi

    const int t    = threadIdx.x;
    const int bm   = blockIdx.y * 128;
    const int bn   = blockIdx.x * 128;
    const int warp = t >> 5;
    const int lane = t & 31;
    const int wm   = (warp & 1) * 64;
    const int wn   = (warp >> 1) * 32;
    const int gid  = lane >> 2;
    const int q    = lane & 3;

    // AROW staging coords
    const int a_r = t >> 2;
    const int a_c = (t & 3) * 4;
    // ACOL staging coords handled inline
    const int b_r = t >> 5;
    const int b_c = (t & 31) * 4;

    // ACOL base: batch slice of x
    const float* Axb = A;
    int hw0 = 0;
    if (ACOL) {
        int batch = bm >> 12;           // /HW
        hw0 = bm & (HW - 1);
        Axb = A + (size_t)batch * K * HW;
    }

    float4 ar[2], br[2];

    float acc[4][4][4];
    #pragma unroll
    for (int mi = 0; mi < 4; mi++)
        #pragma unroll
        for (int ni = 0; ni < 4; ni++)
            #pragma unroll
            for (int r = 0; r < 4; r++) acc[mi][ni][r] = 0.0f;

    const int nk = K >> 4;

    // ---- staging helpers ----
    auto load_chunk = [&](int k0) {
        if (ACOL) {
            #pragma unroll
            for (int i = 0; i < 2; i++) {
                int idx = t + i * 256;          // 0..511
                int k   = idx >> 5;             // 0..15
                int mq  = (idx & 31) * 4;       // 0..124
                ar[i] = *(const float4*)(Axb + (size_t)(k0 + k) * HW + hw0 + mq);
            }
        } else {
            #pragma unroll
            for (int i = 0; i < 2; i++)
                ar[i] = *(const float4*)(A + (size_t)(bm + a_r + i * 64) * K + k0 + a_c);
        }
        #pragma unroll
        for (int i = 0; i < 2; i++)
            br[i] = (bn + b_c < N)
                  ? *(const float4*)(B + (size_t)(k0 + b_r + i * 8) * N + bn + b_c)
                  : make_float4(0.f, 0.f, 0.f, 0.f);
    };

    auto store_chunk = [&](int buf) {
        if (ACOL) {
            #pragma unroll
            for (int i = 0; i < 2; i++) {
                int idx = t + i * 256;
                int k   = idx >> 5;
                int mq  = (idx & 31) * 4;
                uint4 u = make_uint4(f2tf(ar[i].x), f2tf(ar[i].y),
                                     f2tf(ar[i].z), f2tf(ar[i].w));
                *(uint4*)&Ask[buf][k][mq] = u;
            }
        } else {
            #pragma unroll
            for (int i = 0; i < 2; i++) {
                int r = a_r + i * 64;
                As[buf][r][a_c + 0] = f2tf(ar[i].x);
                As[buf][r][a_c + 1] = f2tf(ar[i].y);
                As[buf][r][a_c + 2] = f2tf(ar[i].z);
                As[buf][r][a_c + 3] = f2tf(ar[i].w);
            }
        }
        #pragma unroll
        for (int i = 0; i < 2; i++) {
            int rb = b_r + i * 8;
            Bs[buf][rb][b_c + 0] = f2tf(br[i].x);
            Bs[buf][rb][b_c + 1] = f2tf(br[i].y);
            Bs[buf][rb][b_c + 2] = f2tf(br[i].z);
            Bs[buf][rb][b_c + 3] = f2tf(br[i].w);
        }
    };

    // prologue: chunk 0 -> buf 0
    load_chunk(0);
    store_chunk(0);
    __syncthreads();

    for (int kc = 0; kc < nk; kc++) {
        const int cur = kc & 1;
        const int nxt = cur ^ 1;
        if (kc + 1 < nk) load_chunk((kc + 1) << 4);

        #pragma unroll
        for (int ks = 0; ks < 2; ks++) {
            const int k = ks * 8;
            unsigned af[4][4], bf[4][2];
            #pragma unroll
            for (int mi = 0; mi < 4; mi++) {
                int m0 = wm + mi * 16;
                if (ACOL) {
                    af[mi][0] = Ask[cur][k + q    ][m0 + gid];
                    af[mi][1] = Ask[cur][k + q    ][m0 + gid + 8];
                    af[mi][2] = Ask[cur][k + q + 4][m0 + gid];
                    af[mi][3] = Ask[cur][k + q + 4][m0 + gid + 8];
                } else {
                    af[mi][0] = As[cur][m0 + gid    ][k + q];
                    af[mi][1] = As[cur][m0 + gid + 8][k + q];
                    af[mi][2] = As[cur][m0 + gid    ][k + q + 4];
                    af[mi][3] = As[cur][m0 + gid + 8][k + q + 4];
                }
            }
            #pragma unroll
            for (int ni = 0; ni < 4; ni++) {
                int n0 = wn + ni * 8 + gid;
                bf[ni][0] = Bs[cur][k + q    ][n0];
                bf[ni][1] = Bs[cur][k + q + 4][n0];
            }
            #pragma unroll
            for (int mi = 0; mi < 4; mi++)
                #pragma unroll
                for (int ni = 0; ni < 4; ni++) {
                    asm volatile(
                        "mma.sync.aligned.m16n8k8.row.col.f32.tf32.tf32.f32 "
                        "{%0,%1,%2,%3}, {%4,%5,%6,%7}, {%8,%9}, {%0,%1,%2,%3};\n"
                        : "+f"(acc[mi][ni][0]), "+f"(acc[mi][ni][1]),
                          "+f"(acc[mi][ni][2]), "+f"(acc[mi][ni][3])
                        : "r"(af[mi][0]), "r"(af[mi][1]), "r"(af[mi][2]), "r"(af[mi][3]),
                          "r"(bf[ni][0]), "r"(bf[ni][1]));
                }
        }

        if (kc + 1 < nk) {
            store_chunk(nxt);
            __syncthreads();
        }
    }

    if (OTRANS) {
        // epilogue: BN+ReLU, smem restage, write out[b][c][hw] coalesced
        const int b   = bm >> 12;
        const int h0  = bm & (HW - 1);
        float* outb = C + (size_t)b * N * HW;
        __syncthreads();   // mma consumers done before smem reuse
        #pragma unroll
        for (int g = 0; g < 4; g++) {
            if ((warp >> 1) == g) {
                #pragma unroll
                for (int mi = 0; mi < 4; mi++)
                    #pragma unroll
                    for (int ni = 0; ni < 4; ni++) {
                        int cl = ni * 8 + 2 * q;
                        int colg = bn + 32 * g + cl;
                        float al0 = alpha[colg], al1 = alpha[colg + 1];
                        float be0 = beta[colg],  be1 = beta[colg + 1];
                        #pragma unroll
                        for (int h = 0; h < 2; h++) {
                            int rl = wm + mi * 16 + gid + h * 8;
                            cbuf[cl    ][rl] = fmaxf(acc[mi][ni][2 * h + 0] * al0 + be0, 0.f);
                            cbuf[cl + 1][rl] = fmaxf(acc[mi][ni][2 * h + 1] * al1 + be1, 0.f);
                        }
                    }
            }
            __syncthreads();
            {
                int cl = t >> 3;
                int r0 = (t & 7) * 16;
                int c  = bn + 32 * g + cl;
                float4* dst = (float4*)(outb + (size_t)c * HW + h0 + r0);
                const float* src = &cbuf[cl][r0];
                #pragma unroll
                for (int j = 0; j < 4; j++)
                    dst[j] = *(const float4*)(src + 4 * j);
            }
            __syncthreads();
        }
    } else {
        // standard epilogue (N multiple of 2; cols >= N masked)
        #pragma unroll
        for (int mi = 0; mi < 4; mi++) {
            #pragma unroll
            for (int ni = 0; ni < 4; ni++) {
                int col = bn + wn + ni * 8 + 2 * q;
                if (col >= N) continue;
                float al0 = alpha ? alpha[col]     : 1.0f;
                float al1 = alpha ? alpha[col + 1] : 1.0f;
                float be0 = beta  ? beta[col]      : 0.0f;
                float be1 = beta  ? beta[col + 1]  : 0.0f;
                #pragma unroll
                for (int h = 0; h < 2; h++) {
                    int row = bm + wm + mi * 16 + gid + h * 8;
                    float v0 = acc[mi][ni][2 * h + 0] * al0 + be0;
                    float v1 = acc[mi][ni][2 * h + 1] * al1 + be1;
                    if (do_relu) { v0 = fmaxf(v0, 0.f); v1 = fmaxf(v1, 0.f); }
                    *(float2*)(C + (size_t)row * N + col) = make_float2(v0, v1);
                }
            }
        }
    }
}

// ---------------------------------------------------------------------------
// Small prep kernels
// ---------------------------------------------------------------------------
__global__ void transpose_kernel(const float* __restrict__ in, float* __restrict__ out,
                                 int R, int C)
{
    __shared__ float tile[32][33];
    int c0 = blockIdx.x * 32;
    int r0 = blockIdx.y * 32;
    int x = threadIdx.x, y = threadIdx.y;
    #pragma unroll
    for (int j = 0; j < 32; j += 8)
        tile[y + j][x] = in[(size_t)(r0 + y + j) * C + c0 + x];
    __syncthreads();
    #pragma unroll
    for (int j = 0; j < 32; j += 8)
        out[(size_t)(c0 + y + j) * R + r0 + x] = tile[x][y + j];
}

__global__ void prep_bn_kernel(const float* g1, const float* b1, const float* m1, const float* v1,
                               const float* g2, const float* b2, const float* m2, const float* v2)
{
    int i = threadIdx.x + blockIdx.x * blockDim.x;
    if (i < DMODEL) {
        float a = g1[i] * rsqrtf(v1[i] + EPSV);
        g_alpha1[i] = a;
        g_beta1[i]  = b1[i] - m1[i] * a;
    }
    if (i < CIN) {
        float a = g2[i] * rsqrtf(v2[i] + EPSV);
        g_alpha2[i] = a;
        g_beta2[i]  = b2[i] - m2[i] * a;
    }
}

__global__ void bcast_q_kernel(const float* __restrict__ qe, float* __restrict__ Q)
{
    size_t i = (size_t)blockIdx.x * blockDim.x + threadIdx.x;
    size_t per = (size_t)HW * DMODEL;
    if (i < per) {
        float v = qe[i];
        #pragma unroll
        for (int b = 0; b < BATCH; b++)
            Q[(size_t)b * per + i] = v;
    }
}

// Concat per-layer Woff (D x 64) + Wattn (D x 32) -> WOA [k][n] (D x 96) + bias
__global__ void concat_woa_kernel(const float* __restrict__ Woff_i, const float* __restrict__ boff_i,
                                  const float* __restrict__ Wattn_i, const float* __restrict__ battn_i)
{
    int i = blockIdx.x * blockDim.x + threadIdx.x;
    if (i < DMODEL * NOA) {
        int k = i / NOA, n = i % NOA;
        g_WOA[i] = (n < 64) ? Woff_i[k * 64 + n] : Wattn_i[k * 32 + (n - 64)];
    }
    if (i < NOA)
        g_bOA[i] = (i < 64) ? boff_i[i] : battn_i[i - 64];
}

// ---------------------------------------------------------------------------
// Deformable sampling with fused per-head softmax.
// OA row (stride NOA=96): [offsets: 64][attn logits: 32]
// msel: index mask for OA row (HW-1 for layer 0 broadcast, -1 otherwise)
// ---------------------------------------------------------------------------
__device__ __forceinline__ float fetch_val(const float* __restrict__ vb, int xi, int yi, int c)
{
    if (xi < 0 || xi >= WW || yi < 0 || yi >= HH) return 0.0f;
    return vb[((size_t)(yi * WW + xi)) * DMODEL + c];
}

__global__ void __launch_bounds__(256)
deform_sample_kernel(const float* __restrict__ VAL, const float* __restrict__ OA,
                     float* __restrict__ O, int msel)
{
    int m = blockIdx.x;
    int b = m >> 12;
    int pix = m & (HW - 1);
    int t = threadIdx.x;
    int head = t >> 5;
    int c = t;

    float rx = ((pix & (WW - 1)) + 0.5f) * (1.0f / WW);
    float ry = ((pix >> 6) + 0.5f) * (1.0f / HH);

    int idx = m & msel;
    const float* vb   = VAL + (size_t)b * HW * DMODEL;
    const float* offm = OA + (size_t)idx * NOA + head * (NP * 2);
    const float* lg   = OA + (size_t)idx * NOA + 64 + head * NP;

    float l0 = lg[0], l1 = lg[1], l2 = lg[2], l3 = lg[3];
    float mx = fmaxf(fmaxf(l0, l1), fmaxf(l2, l3));
    float e0 = __expf(l0 - mx), e1 = __expf(l1 - mx);
    float e2 = __expf(l2 - mx), e3 = __expf(l3 - mx);
    float inv = 1.0f / (e0 + e1 + e2 + e3);
    float w[4] = { e0 * inv, e1 * inv, e2 * inv, e3 * inv };

    float acc = 0.0f;
    #pragma unroll
    for (int p = 0; p < NP; p++) {
        float lx = rx + offm[p * 2 + 0] * (1.0f / WW);
        float ly = ry + offm[p * 2 + 1] * (1.0f / HH);
        float gx = lx * WW - 0.5f;
        float gy = ly * HH - 0.5f;
        float fx = floorf(gx), fy = floorf(gy);
        int x0 = (int)fx, y0 = (int)fy;
        float wx = gx - fx, wy = gy - fy;
        float v00 = fetch_val(vb, x0,     y0,     c);
        float v10 = fetch_val(vb, x0 + 1, y0,     c);
        float v01 = fetch_val(vb, x0,     y0 + 1, c);
        float v11 = fetch_val(vb, x0 + 1, y0 + 1, c);
        float s = v00 * (1.f - wx) * (1.f - wy) + v10 * wx * (1.f - wy)
                + v01 * (1.f - wx) * wy         + v11 * wx * wy;
        acc = fmaf(w[p], s, acc);
    }
    O[(size_t)m * DMODEL + c] = acc;
}

// ---------------------------------------------------------------------------
// Residual + LayerNorm (in place on Q)
// ---------------------------------------------------------------------------
__global__ void __launch_bounds__(256)
resid_ln_kernel(float* __restrict__ Q, const float* __restrict__ T,
                const float* __restrict__ gamma, const float* __restrict__ beta)
{
    int row  = blockIdx.x * 8 + (threadIdx.x >> 5);
    int lane = threadIdx.x & 31;
    const float4* qr = (const float4*)(Q + (size_t)row * DMODEL);
    const float4* tr = (const float4*)(T + (size_t)row * DMODEL);

    float x[8];
    float sum = 0.f, sumsq = 0.f;
    #pragma unroll
    for (int i = 0; i < 2; i++) {
        float4 a = qr[lane + i * 32];
        float4 b = tr[lane + i * 32];
        float v0 = a.x + b.x, v1 = a.y + b.y, v2 = a.z + b.z, v3 = a.w + b.w;
        x[i * 4 + 0] = v0; x[i * 4 + 1] = v1; x[i * 4 + 2] = v2; x[i * 4 + 3] = v3;
        sum += v0 + v1 + v2 + v3;
        sumsq += v0 * v0 + v1 * v1 + v2 * v2 + v3 * v3;
    }
    #pragma unroll
    for (int s = 16; s > 0; s >>= 1) {
        sum   += __shfl_xor_sync(0xffffffffu, sum, s);
        sumsq += __shfl_xor_sync(0xffffffffu, sumsq, s);
    }
    float mean = sum * (1.0f / DMODEL);
    float var  = sumsq * (1.0f / DMODEL) - mean * mean;
    float rstd = rsqrtf(var + EPSV);

    float4* qw = (float4*)(Q + (size_t)row * DMODEL);
    #pragma unroll
    for (int i = 0; i < 2; i++) {
        int e = (lane + i * 32) * 4;
        float4 o;
        o.x = (x[i * 4 + 0] - mean) * rstd * gamma[e + 0] + beta[e + 0];
        o.y = (x[i * 4 + 1] - mean) * rstd * gamma[e + 1] + beta[e + 1];
        o.z = (x[i * 4 + 2] - mean) * rstd * gamma[e + 2] + beta[e + 2];
        o.w = (x[i * 4 + 3] - mean) * rstd * gamma[e + 3] + beta[e + 3];
        qw[lane + i * 32] = o;
    }
}

// ---------------------------------------------------------------------------
// Launch
// ---------------------------------------------------------------------------
extern "C" void kernel_launch(void* const* d_in, const int* in_sizes, int n_in,
                              void* d_out, int out_size)
{
    const float* x      = (const float*)d_in[0];
    const float* W_in   = (const float*)d_in[1];
    const float* bn1_g  = (const float*)d_in[2];
    const float* bn1_b  = (const float*)d_in[3];
    const float* bn1_m  = (const float*)d_in[4];
    const float* bn1_v  = (const float*)d_in[5];
    const float* qembed = (const float*)d_in[6];
    const float* Woff   = (const float*)d_in[7];
    const float* boff   = (const float*)d_in[8];
    const float* Wattn  = (const float*)d_in[9];
    const float* battn  = (const float*)d_in[10];
    const float* Wval   = (const float*)d_in[11];
    const float* bval   = (const float*)d_in[12];
    const float* Wo     = (const float*)d_in[13];
    const float* bo     = (const float*)d_in[14];
    const float* ln1_g  = (const float*)d_in[15];
    const float* ln1_b  = (const float*)d_in[16];
    const float* W1     = (const float*)d_in[17];
    const float* b1     = (const float*)d_in[18];
    const float* W2     = (const float*)d_in[19];
    const float* b2     = (const float*)d_in[20];
    const float* ln2_g  = (const float*)d_in[21];
    const float* ln2_b  = (const float*)d_in[22];
    const float* W_out  = (const float*)d_in[23];
    const float* bn2_g  = (const float*)d_in[24];
    const float* bn2_b  = (const float*)d_in[25];
    const float* bn2_m  = (const float*)d_in[26];
    const float* bn2_v  = (const float*)d_in[27];
    float* out = (float*)d_out;

    float *SRC, *Q, *VAL, *T1, *OA, *H, *WIT, *WOT, *WOA, *bOA;
    float *al1, *be1, *al2, *be2;
    cudaGetSymbolAddress((void**)&SRC, g_SRC);
    cudaGetSymbolAddress((void**)&Q,   g_Q);
    cudaGetSymbolAddress((void**)&VAL, g_VAL);
    cudaGetSymbolAddress((void**)&T1,  g_T1);
    cudaGetSymbolAddress((void**)&OA,  g_OA);
    cudaGetSymbolAddress((void**)&H,   g_H);
    cudaGetSymbolAddress((void**)&WIT, g_WIT);
    cudaGetSymbolAddress((void**)&WOT, g_WOT);
    cudaGetSymbolAddress((void**)&WOA, g_WOA);
    cudaGetSymbolAddress((void**)&bOA, g_bOA);
    cudaGetSymbolAddress((void**)&al1, g_alpha1);
    cudaGetSymbolAddress((void**)&be1, g_beta1);
    cudaGetSymbolAddress((void**)&al2, g_alpha2);
    cudaGetSymbolAddress((void**)&be2, g_beta2);

    dim3 tb32(32, 8);

    // prep: BN params, W_in^T, W_out^T, broadcast Q
    prep_bn_kernel<<<1, 512>>>(bn1_g, bn1_b, bn1_m, bn1_v, bn2_g, bn2_b, bn2_m, bn2_v);
    transpose_kernel<<<dim3(CIN / 32, DMODEL / 32), tb32>>>(W_in, WIT, DMODEL, CIN);
    transpose_kernel<<<dim3(DMODEL / 32, CIN / 32), tb32>>>(W_out, WOT, CIN, DMODEL);
    {
        int per = HW * DMODEL;
        bcast_q_kernel<<<(per + 255) / 256, 256>>>(qembed, Q);
    }

    // proj_in: A = x directly (ACOL), B = W_in^T, fused BN+ReLU epilogue
    gemm_tf32_kernel<1, 0><<<dim3(DMODEL / 128, MROWS / 128), 256>>>(
        x, WIT, SRC, MROWS, DMODEL, CIN, al1, be1, 1);

    for (int i = 0; i < LNUM; i++) {
        const float* Wval_i  = Wval  + (size_t)i * DMODEL * DMODEL;
        const float* bval_i  = bval  + (size_t)i * DMODEL;
        const float* Woff_i  = Woff  + (size_t)i * DMODEL * (NH * NP * 2);
        const float* boff_i  = boff  + (size_t)i * (NH * NP * 2);
        const float* Wattn_i = Wattn + (size_t)i * DMODEL * (NH * NP);
        const float* battn_i = battn + (size_t)i * (NH * NP);
        const float* Wo_i    = Wo    + (size_t)i * DMODEL * DMODEL;
        const float* bo_i    = bo    + (size_t)i * DMODEL;
        const float* W1_i    = W1    + (size_t)i * DMODEL * DFF;
        const float* b1_i    = b1    + (size_t)i * DFF;
        const float* W2_i    = W2    + (size_t)i * DFF * DMODEL;
        const float* b2_i    = b2    + (size_t)i * DMODEL;

        concat_woa_kernel<<<(DMODEL * NOA + 255) / 256, 256>>>(Woff_i, boff_i,
                                                               Wattn_i, battn_i);

        gemm_tf32_kernel<0, 0><<<dim3(DMODEL / 128, MROWS / 128), 256>>>(
            SRC, Wval_i, VAL, MROWS, DMODEL, DMODEL, nullptr, bval_i, 0);

        // offsets + attn logits. Layer 0: Q is batch-broadcast -> compute
        // only HW rows and let the sampler index by pixel.
        int oam  = (i == 0) ? HW : MROWS;
        int msel = (i == 0) ? (HW - 1) : -1;
        gemm_tf32_kernel<0, 0><<<dim3(1, oam / 128), 256>>>(
            Q, WOA, OA, oam, NOA, DMODEL, nullptr, bOA, 0);

        deform_sample_kernel<<<MROWS, 256>>>(VAL, OA, H, msel);

        gemm_tf32_kernel<0, 0><<<dim3(DMODEL / 128, MROWS / 128), 256>>>(
            H, Wo_i, T1, MROWS, DMODEL, DMODEL, nullptr, bo_i, 0);
        resid_ln_kernel<<<MROWS / 8, 256>>>(Q, T1, ln1_g + (size_t)i * DMODEL,
                                            ln1_b + (size_t)i * DMODEL);
        gemm_tf32_kernel<0, 0><<<dim3(DFF / 128, MROWS / 128), 256>>>(
            Q, W1_i, H, MROWS, DFF, DMODEL, nullptr, b1_i, 1);
        gemm_tf32_kernel<0, 0><<<dim3(DMODEL / 128, MROWS / 128), 256>>>(
            H, W2_i, T1, MROWS, DMODEL, DFF, nullptr, b2_i, 0);
        resid_ln_kernel<<<MROWS / 8, 256>>>(Q, T1, ln2_g + (size_t)i * DMODEL,
                                            ln2_b + (size_t)i * DMODEL);
    }

    // proj_out: fused BN+ReLU+transpose epilogue writes out[b][c][hw]
    gemm_tf32_kernel<0, 1><<<dim3(CIN / 128, MROWS / 128), 256>>>(
        Q, WOT, out, MROWS, CIN, DMODEL, al2, be2, 1);
}